// round 16
// baseline (speedup 1.0000x reference)
#include <cuda_runtime.h>
#include <cuda_bf16.h>

// y[b,n] = x[b,n] * W[n],  W[n] = sum over valid frames m of aw[j]*sw[j],
// j = (n mod 256) + 256*m, m in [max(0, q-8188), min(3, q)], q = n/256.
// Diagonal-operator collapse -> pure touch-once stream (128 MiB r + 128 MiB w).
//
// Body identical to the session-best (R5/R15: two batches of 8, MLP=8,
// vectorized prologue, ldcg/stcg). This round sweeps the one untouched
// geometry knob: CTA shape 2048x256 -> 1024x512 (same 524,288 threads,
// same per-thread work and phase invariants; only scheduling granularity
// changes).

#define HOPC      256u
#define NSAMP     (1u << 21)          // samples per row
#define NROWS     16u
#define QMAXV     8188u               // num_segments - 1
#define N4ROW     (NSAMP / 4u)        // 524,288 float4 per row
#define NBLK      1024u
#define NTHR      512u

__global__ void __launch_bounds__(NTHR)
segmenter_roundtrip_kernel(const float4* __restrict__ x,
                           const float4* __restrict__ aw4,
                           const float4* __restrict__ sw4,
                           float4*       __restrict__ y) {
    const unsigned base = blockIdx.x * NTHR + threadIdx.x;  // f4 idx in row

    const unsigned n  = base << 2;               // sample index within row
    const unsigned q  = n >> 8;                  // frame-phase index
    const unsigned r4 = (n & (HOPC - 1u)) >> 2;  // float4 index of r

    // Truncated frame range (interior: [0,3]).
    const int m_lo = (q > QMAXV) ? (int)(q - QMAXV) : 0;
    const int m_hi = (q < 3u) ? (int)q : 3;

    // Per-thread weights: 8 vector loads total (windows L1/L2-hot).
    float w0 = 0.f, w1 = 0.f, w2 = 0.f, w3 = 0.f;
#pragma unroll
    for (int m = 0; m < 4; ++m) {
        const float mask = (m >= m_lo && m <= m_hi) ? 1.0f : 0.0f;
        const float4 a = aw4[r4 + (unsigned)m * (HOPC / 4u)];
        const float4 s = sw4[r4 + (unsigned)m * (HOPC / 4u)];
        w0 += mask * a.x * s.x;
        w1 += mask * a.y * s.y;
        w2 += mask * a.z * s.z;
        w3 += mask * a.w * s.w;
    }

    // 16 rows, two batches of 8 (MLP=8 within a batch, 32 data regs).
#pragma unroll
    for (unsigned b = 0; b < 2; ++b) {
        float4 v[8];
#pragma unroll
        for (unsigned k = 0; k < 8; ++k)
            v[k] = __ldcg(&x[(b * 8u + k) * N4ROW + base]);
#pragma unroll
        for (unsigned k = 0; k < 8; ++k) {
            float4 t = v[k];
            t.x *= w0; t.y *= w1; t.z *= w2; t.w *= w3;
            __stcg(&y[(b * 8u + k) * N4ROW + base], t);
        }
    }
}

extern "C" void kernel_launch(void* const* d_in, const int* in_sizes, int n_in,
                              void* d_out, int out_size) {
    const float4* x  = (const float4*)d_in[0];
    const float4* aw = (const float4*)d_in[1];
    const float4* sw = (const float4*)d_in[2];
    float4*       y  = (float4*)d_out;

    (void)in_sizes; (void)n_in; (void)out_size;

    segmenter_roundtrip_kernel<<<NBLK, NTHR>>>(x, aw, sw, y);
}